// round 15
// baseline (speedup 1.0000x reference)
#include <cuda_runtime.h>
#include <cuda_fp16.h>
#include <math.h>
#include <stdint.h>

// Problem dims (fixed by reference setup_inputs)
#define B_   4
#define L_   2048
#define D_   1024
#define DF_  4096
#define M_   (B_ * L_)        // 8192 rows
#define NC_  32               // scan chunks along L
#define CL_  (L_ / NC_)       // 64
#define BLD  (B_ * L_ * D_)   // 8388608

// ---------------- scratch (device globals; no allocation allowed) ----------
__device__ float  g_s [BLD];
__device__ float  g_h [BLD];
__device__ float2 g_E [B_ * NC_ * D_];
__device__ float2 g_T [B_ * NC_ * D_];
__device__ float2 g_stat[M_];          // per-row (mean, rstd) of x
// fp16 operands (plain fp16 both sides)
__device__ __half g_xH  [M_ * D_];
__device__ __half g_hnH [M_ * D_];
__device__ __half g_tH  [M_ * DF_];
__device__ __half g_fcwH[D_  * D_];
__device__ __half g_w1H [DF_ * D_];
__device__ __half g_w2H [D_  * DF_];

// ======================= helpers ===========================================
__device__ __forceinline__ uint32_t smem_u32(const void* p) {
    return (uint32_t)__cvta_generic_to_shared(p);
}
__device__ __forceinline__ uint32_t packh2(__half a, __half b) {
    __half2 t = __halves2half2(a, b);
    return *reinterpret_cast<uint32_t*>(&t);
}

// ---------------- merged fp16 weight convert --------------------------------
#define W0Q ((D_ * D_) / 4)
#define W1Q ((DF_ * D_) / 4)
#define W2Q ((D_ * DF_) / 4)
__global__ void conv_weights(const float* __restrict__ fcw,
                             const float* __restrict__ w1,
                             const float* __restrict__ w2,
                             __half* __restrict__ ofc,
                             __half* __restrict__ ow1,
                             __half* __restrict__ ow2)
{
    const int total = W0Q + W1Q + W2Q;
    for (int q = blockIdx.x * blockDim.x + threadIdx.x; q < total;
         q += gridDim.x * blockDim.x) {
        const float* in;
        __half* out;
        int i;
        if (q < W0Q)            { in = fcw; out = ofc; i = q; }
        else if (q < W0Q + W1Q) { in = w1;  out = ow1; i = q - W0Q; }
        else                    { in = w2;  out = ow2; i = q - W0Q - W1Q; }
        const float4 v = *reinterpret_cast<const float4*>(in + i * 4);
        *reinterpret_cast<uint2*>(out + i * 4) =
            make_uint2(packh2(__float2half_rn(v.x), __float2half_rn(v.y)),
                       packh2(__float2half_rn(v.z), __float2half_rn(v.w)));
    }
}

// ---------------- LN stats (first LN) + raw-x fp16 convert ------------------
__global__ void ln_stats(const float* __restrict__ x, __half* __restrict__ sp)
{
    const int row = blockIdx.x;
    const int tid = threadIdx.x;
    const float4 v = reinterpret_cast<const float4*>(x + (size_t)row * D_)[tid];

    float s  = v.x + v.y + v.z + v.w;
    float ss = v.x*v.x + v.y*v.y + v.z*v.z + v.w*v.w;
    #pragma unroll
    for (int o = 16; o; o >>= 1) {
        s  += __shfl_xor_sync(0xffffffffu, s,  o);
        ss += __shfl_xor_sync(0xffffffffu, ss, o);
    }
    __shared__ float shs[8], shq[8];
    const int w = tid >> 5, ln = tid & 31;
    if (ln == 0) { shs[w] = s; shq[w] = ss; }
    __syncthreads();
    s = 0.f; ss = 0.f;
    #pragma unroll
    for (int i = 0; i < 8; i++) { s += shs[i]; ss += shq[i]; }

    const float mean = s * (1.0f / D_);
    const float var  = ss * (1.0f / D_) - mean * mean;
    const float rstd = rsqrtf(var + 1e-5f);
    if (tid == 0) g_stat[row] = make_float2(mean, rstd);

    *reinterpret_cast<uint2*>(sp + (size_t)row * D_ + tid*4) =
        make_uint2(packh2(__float2half_rn(v.x), __float2half_rn(v.y)),
                   packh2(__float2half_rn(v.z), __float2half_rn(v.w)));
}

// ---------------- LayerNorm (second LN: full, fp16 out) ---------------------
__global__ void ln_kernel(const float* __restrict__ x,
                          const float* __restrict__ g,
                          const float* __restrict__ bb,
                          __half* __restrict__ sp)
{
    const int row = blockIdx.x;
    const int tid = threadIdx.x;
    const float4 v = reinterpret_cast<const float4*>(x + (size_t)row * D_)[tid];

    float s  = v.x + v.y + v.z + v.w;
    float ss = v.x*v.x + v.y*v.y + v.z*v.z + v.w*v.w;
    #pragma unroll
    for (int o = 16; o; o >>= 1) {
        s  += __shfl_xor_sync(0xffffffffu, s,  o);
        ss += __shfl_xor_sync(0xffffffffu, ss, o);
    }
    __shared__ float shs[8], shq[8];
    const int w = tid >> 5, ln = tid & 31;
    if (ln == 0) { shs[w] = s; shq[w] = ss; }
    __syncthreads();
    s = 0.f; ss = 0.f;
    #pragma unroll
    for (int i = 0; i < 8; i++) { s += shs[i]; ss += shq[i]; }

    const float mean = s * (1.0f / D_);
    const float var  = ss * (1.0f / D_) - mean * mean;
    const float rstd = rsqrtf(var + 1e-5f);

    const float4 gg = reinterpret_cast<const float4*>(g)[tid];
    const float4 bv = reinterpret_cast<const float4*>(bb)[tid];
    const float o0 = (v.x - mean) * rstd * gg.x + bv.x;
    const float o1 = (v.y - mean) * rstd * gg.y + bv.y;
    const float o2 = (v.z - mean) * rstd * gg.z + bv.z;
    const float o3 = (v.w - mean) * rstd * gg.w + bv.w;

    *reinterpret_cast<uint2*>(sp + (size_t)row * D_ + tid*4) =
        make_uint2(packh2(__float2half_rn(o0), __float2half_rn(o1)),
                   packh2(__float2half_rn(o2), __float2half_rn(o3)));
}

// ---------------- spiral-conv scan (3-pass, R12-proven) ----------------------
__device__ __forceinline__ void phazor_a(float pr, float pi, float& ar, float& ai)
{
    const float amag = sqrtf(pr*pr + pi*pi);
    const float e = expf(-amag) / amag;
    ar = pr * e; ai = pi * e;
}

__global__ void scan_pass1(const float* __restrict__ x,
                           const float* __restrict__ lng, const float* __restrict__ lnb,
                           const float* __restrict__ phr, const float* __restrict__ phi,
                           const float* __restrict__ pir, const float* __restrict__ pii)
{
    __shared__ float2 st[CL_];
    const int tid   = threadIdx.x;
    const int chunk = blockIdx.x;
    const int bd    = blockIdx.y;
    const int b     = bd >> 2;
    const int d     = ((bd & 3) << 8) + tid;

    if (tid < CL_) st[tid] = g_stat[b * L_ + chunk * CL_ + tid];
    __syncthreads();

    float ar, ai; phazor_a(phr[d], phi[d], ar, ai);
    const float ir = pir[d], ii = pii[d];
    const float gam = lng[d], bet = lnb[d];

    float cr = 0.f, ci = 0.f;
    const float* xp = x + ((size_t)b * L_ + (size_t)chunk * CL_) * D_ + d;
    #pragma unroll 4
    for (int l = 0; l < CL_; l++) {
        const float2 sr = st[l];
        const float xv = fmaf((xp[(size_t)l * D_] - sr.x) * sr.y, gam, bet);
        const float nr = fmaf(ar, cr, fmaf(-ai, ci, ir * xv));
        const float ni = fmaf(ar, ci, fmaf( ai, cr, ii * xv));
        cr = nr; ci = ni;
    }
    g_E[((size_t)b * NC_ + chunk) * D_ + d] = make_float2(cr, ci);
}

__global__ void scan_pass2(const float* __restrict__ hr, const float* __restrict__ hi,
                           const float* __restrict__ phr, const float* __restrict__ phi)
{
    const int tid = threadIdx.x;
    const int bd  = blockIdx.x;
    const int b   = bd >> 2;
    const int d   = ((bd & 3) << 8) + tid;

    float ar, ai; phazor_a(phr[d], phi[d], ar, ai);
    float qr = ar, qi = ai;        // a^64 via 6 squarings
    #pragma unroll
    for (int i = 0; i < 6; i++) {
        const float nr = qr*qr - qi*qi;
        const float ni = 2.f * qr * qi;
        qr = nr; qi = ni;
    }
    float tr = hr[b * D_ + d], ti = hi[b * D_ + d];

    const float2* Ep = g_E + (size_t)b * NC_ * D_ + d;
    float2*       Tp = g_T + (size_t)b * NC_ * D_ + d;

    #pragma unroll
    for (int g = 0; g < NC_ / 8; g++) {
        float2 ev[8];
        #pragma unroll
        for (int j = 0; j < 8; j++)
            ev[j] = Ep[(size_t)(g * 8 + j) * D_];
        #pragma unroll
        for (int j = 0; j < 8; j++) {
            Tp[(size_t)(g * 8 + j) * D_] = make_float2(tr, ti);
            const float nr = qr*tr - qi*ti + ev[j].x;
            const float ni = qr*ti + qi*tr + ev[j].y;
            tr = nr; ti = ni;
        }
    }
}

__global__ void scan_pass3(const float* __restrict__ x,
                           const float* __restrict__ lng, const float* __restrict__ lnb,
                           const float* __restrict__ phr, const float* __restrict__ phi,
                           const float* __restrict__ pir, const float* __restrict__ pii,
                           float2* __restrict__ cwp_out,
                           float*  __restrict__ s_extra)
{
    __shared__ float2 st[CL_];
    const int tid   = threadIdx.x;
    const int chunk = blockIdx.x;
    const int bd    = blockIdx.y;
    const int b     = bd >> 2;
    const int d     = ((bd & 3) << 8) + tid;

    if (tid < CL_) st[tid] = g_stat[b * L_ + chunk * CL_ + tid];
    __syncthreads();

    float ar, ai; phazor_a(phr[d], phi[d], ar, ai);
    const float ir = pir[d], ii = pii[d];
    const float gam = lng[d], bet = lnb[d];

    const float2 t0 = g_T[((size_t)b * NC_ + chunk) * D_ + d];
    float cr = t0.x, ci = t0.y;

    const size_t base = ((size_t)b * L_ + (size_t)chunk * CL_) * D_ + d;
    #pragma unroll 4
    for (int l = 0; l < CL_; l++) {
        const size_t idx = base + (size_t)l * D_;
        const float2 sr = st[l];
        const float xv = fmaf((x[idx] - sr.x) * sr.y, gam, bet);
        const float nr = fmaf(ar, cr, fmaf(-ai, ci, ir * xv));
        const float ni = fmaf(ar, ci, fmaf( ai, cr, ii * xv));
        cr = nr; ci = ni;
        g_s[idx] = cr;
        if (cwp_out) cwp_out[idx] = make_float2(cr, ci);
        if (s_extra) s_extra[idx] = cr;
    }
}

// =================== fp16 HMMA NT GEMM  (mma.sync m16n8k16) ================
// BM=128 BN=128, 128 threads (4 warps, 64x64 warp tile), 3-stage multistage,
// 2 CTAs per SM, persistent CTAs.  (R14-proven — unchanged.)

#define GTHREADS 128
#define ASUBB   8192
#define BSUBB   8192
#define SUBB    (ASUBB + BSUBB)
#define STAGE64 (2 * SUBB)
#define GSTAGES 3
#define GSMEM   (GSTAGES * STAGE64)

__device__ __forceinline__ void cp_async16(uint32_t saddr, const void* gaddr) {
    asm volatile("cp.async.cg.shared.global [%0], [%1], 16;\n"
                 :: "r"(saddr), "l"(gaddr) : "memory");
}
__device__ __forceinline__ void cp_commit() {
    asm volatile("cp.async.commit_group;\n" ::: "memory");
}
__device__ __forceinline__ void cp_wait1() {
    asm volatile("cp.async.wait_group 1;\n" ::: "memory");
}
__device__ __forceinline__ void cp_wait0() {
    asm volatile("cp.async.wait_group 0;\n" ::: "memory");
}
__device__ __forceinline__ void ldmatrix_x4(uint32_t* r, uint32_t addr) {
    asm volatile("ldmatrix.sync.aligned.m8n8.x4.shared.b16 {%0,%1,%2,%3}, [%4];\n"
                 : "=r"(r[0]), "=r"(r[1]), "=r"(r[2]), "=r"(r[3]) : "r"(addr));
}
#define MMA16816(ac, a, b0v, b1v) \
    asm volatile("mma.sync.aligned.m16n8k16.row.col.f32.f16.f16.f32 " \
        "{%0,%1,%2,%3}, {%4,%5,%6,%7}, {%8,%9}, {%0,%1,%2,%3};\n" \
        : "+f"((ac)[0]), "+f"((ac)[1]), "+f"((ac)[2]), "+f"((ac)[3]) \
        : "r"((a)[0]), "r"((a)[1]), "r"((a)[2]), "r"((a)[3]), "r"(b0v), "r"(b1v))

__device__ __forceinline__ void gemm_load_stage64(const __half* __restrict__ Ab,
                                                  const __half* __restrict__ Bb,
                                                  int K, int kt64, char* sm, int tid)
{
    #pragma unroll
    for (int sub = 0; sub < 2; sub++) {
        const int k0 = kt64 * 64 + sub * 32;
        char* s = sm + sub * SUBB;
        #pragma unroll
        for (int h = 0; h < 4; h++) {
            const int ci  = h * GTHREADS + tid;
            const int row = ci >> 2;
            const int c   = ci & 3;
            const int sw  = (c ^ ((row >> 1) & 3)) << 4;
            cp_async16(smem_u32(s + row * 64 + sw), Ab + (size_t)row * K + k0 + c * 8);
        }
        #pragma unroll
        for (int h = 0; h < 4; h++) {
            const int ci  = h * GTHREADS + tid;
            const int row = ci >> 2;
            const int c   = ci & 3;
            const int sw  = (c ^ ((row >> 1) & 3)) << 4;
            cp_async16(smem_u32(s + ASUBB + row * 64 + sw), Bb + (size_t)row * K + k0 + c * 8);
        }
    }
}

template<int EPI>   // 0: h=s*silu(v)+x (f32)  1: silu(v) fp16  2: v+h (f32/cplx)
__global__ void __launch_bounds__(GTHREADS, 2)
gemm_mma(const __half* __restrict__ A, const __half* __restrict__ Bm,
         const float* __restrict__ bias,
         const float* __restrict__ aux1, const float* __restrict__ aux2,
         void* __restrict__ Cout, int out_mul, int N, int K)
{
    extern __shared__ __align__(16) char smem[];

    const int tid  = threadIdx.x;
    const int wid  = tid >> 5, lane = tid & 31;
    const int wm   = wid & 1;
    const int wn   = wid >> 1;
    const int NK   = K / 64;

    const int rA   = wm * 64 + (lane & 15);
    const int rB   = wn * 64 + (lane & 15);
    const int khalf = lane >> 4;
    const int swA  = (rA >> 1) & 3;
    const int swB  = (rB >> 1) & 3;
    const int tr   = lane >> 2;
    const int tc   = (lane & 3) * 2;

    const int nbn = N / 128;
    const int ntiles = (M_ / 128) * nbn;

    for (int t = blockIdx.x; t < ntiles; t += gridDim.x) {
        const int bn = t % nbn, bm = t / nbn;
        const __half* Ab = A  + (size_t)(bm * 128) * K;
        const __half* Bb = Bm + (size_t)(bn * 128) * K;

        float acc[4][8][4];
        #pragma unroll
        for (int i = 0; i < 4; i++)
            #pragma unroll
            for (int j = 0; j < 8; j++)
                #pragma unroll
                for (int q = 0; q < 4; q++) acc[i][j][q] = 0.f;

        gemm_load_stage64(Ab, Bb, K, 0, smem, tid);
        cp_commit();
        gemm_load_stage64(Ab, Bb, K, 1, smem + STAGE64, tid);
        cp_commit();

        for (int kt = 0; kt < NK; kt++) {
            cp_wait1();
            __syncthreads();

            if (kt + 2 < NK)
                gemm_load_stage64(Ab, Bb, K, kt + 2,
                                  smem + ((kt + 2) % GSTAGES) * STAGE64, tid);
            cp_commit();

            char* stg = smem + (kt % GSTAGES) * STAGE64;
            #pragma unroll
            for (int sub = 0; sub < 2; sub++) {
                char* sm = stg + sub * SUBB;
                const uint32_t aBase = smem_u32(sm) + rA * 64;
                const uint32_t bBase = smem_u32(sm + ASUBB) + rB * 64;
                #pragma unroll
                for (int ks = 0; ks < 2; ks++) {
                    uint32_t af[4][4], bfr[4][4];
                    const int chA = ((ks * 2 + khalf) ^ swA) << 4;
                    const int chB = ((ks * 2 + khalf) ^ swB) << 4;
                    #pragma unroll
                    for (int mi = 0; mi < 4; mi++)
                        ldmatrix_x4(af[mi], aBase + mi * 1024 + chA);
                    #pragma unroll
                    for (int bj = 0; bj < 4; bj++)
                        ldmatrix_x4(bfr[bj], bBase + bj * 1024 + chB);
                    #pragma unroll
                    for (int mi = 0; mi < 4; mi++)
                        #pragma unroll
                        for (int nj = 0; nj < 8; nj++)
                            MMA16816(acc[mi][nj], af[mi],
                                     bfr[nj >> 1][nj & 1], bfr[nj >> 1][(nj & 1) + 2]);
                }
            }
        }
        cp_wait0();
        __syncthreads();

        // ---- epilogue ----
        #pragma unroll
        for (int mi = 0; mi < 4; mi++) {
            #pragma unroll
            for (int r2 = 0; r2 < 2; r2++) {
                const size_t grow = (size_t)bm * 128 + wm * 64 + mi * 16 + tr + r2 * 8;
                #pragma unroll
                for (int nj = 0; nj < 8; nj++) {
                    const int gcol = bn * 128 + wn * 64 + nj * 8 + tc;
                    float v0 = acc[mi][nj][r2 * 2]     + bias[gcol];
                    float v1 = acc[mi][nj][r2 * 2 + 1] + bias[gcol + 1];
                    const size_t idx = grow * (size_t)N + gcol;
                    if (EPI == 0) {
                        const float2 a1 = *reinterpret_cast<const float2*>(aux1 + idx);
                        const float2 a2 = *reinterpret_cast<const float2*>(aux2 + idx);
                        v0 = a1.x * (v0 / (1.f + __expf(-v0))) + a2.x;
                        v1 = a1.y * (v1 / (1.f + __expf(-v1))) + a2.y;
                        *reinterpret_cast<float2*>((float*)Cout + idx) = make_float2(v0, v1);
                    } else if (EPI == 1) {
                        v0 = v0 / (1.f + __expf(-v0));
                        v1 = v1 / (1.f + __expf(-v1));
                        __half* T = (__half*)Cout;
                        *reinterpret_cast<uint32_t*>(T + idx) =
                            packh2(__float2half_rn(v0), __float2half_rn(v1));
                    } else {
                        const float2 a1 = *reinterpret_cast<const float2*>(aux1 + idx);
                        v0 += a1.x; v1 += a1.y;
                        if (out_mul == 2) {
                            float* C = (float*)Cout;
                            C[idx * 2]     = v0; C[idx * 2 + 1] = 0.f;
                            C[idx * 2 + 2] = v1; C[idx * 2 + 3] = 0.f;
                        } else {
                            *reinterpret_cast<float2*>((float*)Cout + idx) = make_float2(v0, v1);
                        }
                    }
                }
            }
        }
        __syncthreads();
    }
}

// ---------------- launch ---------------------------------------------------
extern "C" void kernel_launch(void* const* d_in, const int* in_sizes, int n_in,
                              void* d_out, int out_size)
{
    const float* x     = (const float*)d_in[0];
    const float* hr    = (const float*)d_in[1];
    const float* hi    = (const float*)d_in[2];
    const float* phr   = (const float*)d_in[3];
    const float* phi   = (const float*)d_in[4];
    const float* pir   = (const float*)d_in[5];
    const float* pii   = (const float*)d_in[6];
    const float* gamma = (const float*)d_in[7];
    const float* beta  = (const float*)d_in[8];
    const float* fc_w  = (const float*)d_in[9];
    const float* fc_b  = (const float*)d_in[10];
    const float* w1    = (const float*)d_in[11];
    const float* b1    = (const float*)d_in[12];
    const float* w2    = (const float*)d_in[13];
    const float* b2    = (const float*)d_in[14];
    float* out = (float*)d_out;

    float *p_s, *p_h;
    __half *p_xH, *p_hnH, *p_tH, *p_fcwH, *p_w1H, *p_w2H;
    cudaGetSymbolAddress((void**)&p_s,    g_s);
    cudaGetSymbolAddress((void**)&p_h,    g_h);
    cudaGetSymbolAddress((void**)&p_xH,   g_xH);
    cudaGetSymbolAddress((void**)&p_hnH,  g_hnH);
    cudaGetSymbolAddress((void**)&p_tH,   g_tH);
    cudaGetSymbolAddress((void**)&p_fcwH, g_fcwH);
    cudaGetSymbolAddress((void**)&p_w1H,  g_w1H);
    cudaGetSymbolAddress((void**)&p_w2H,  g_w2H);

    cudaFuncSetAttribute(gemm_mma<0>, cudaFuncAttributeMaxDynamicSharedMemorySize, GSMEM);
    cudaFuncSetAttribute(gemm_mma<1>, cudaFuncAttributeMaxDynamicSharedMemorySize, GSMEM);
    cudaFuncSetAttribute(gemm_mma<2>, cudaFuncAttributeMaxDynamicSharedMemorySize, GSMEM);

    int nsm = 148;
    cudaDeviceGetAttribute(&nsm, cudaDevAttrMultiProcessorCount, 0);
    const int ngrid = 2 * nsm;

    // one-time stream/event objects (host-side only; no device memory)
    static cudaStream_t s2 = nullptr;
    static cudaEvent_t  evFork = nullptr, evJoin = nullptr;
    if (!s2) {
        cudaStreamCreateWithFlags(&s2, cudaStreamNonBlocking);
        cudaEventCreateWithFlags(&evFork, cudaEventDisableTiming);
        cudaEventCreateWithFlags(&evJoin, cudaEventDisableTiming);
    }

    // Adapt to output packing (second output new_hidden is complex64 [B,L,D])
    float2* cwp_out = nullptr;
    float*  s_extra = nullptr;
    int out_mul = 1;
    if (out_size == 3 * BLD) {
        cwp_out = (float2*)(out + (size_t)BLD);
    } else if (out_size == 4 * BLD) {
        out_mul = 2;
        cwp_out = (float2*)(out + 2 * (size_t)BLD);
    } else if (out_size == 2 * BLD) {
        s_extra = out + (size_t)BLD;
    }

    // 0) fork: fp16 weight conversion on side stream (independent of scan chain)
    cudaEventRecord(evFork, 0);
    cudaStreamWaitEvent(s2, evFork, 0);
    conv_weights<<<1024, 256, 0, s2>>>(fc_w, w1, w2, p_fcwH, p_w1H, p_w2H);
    cudaEventRecord(evJoin, s2);

    // 1) per-row LN stats of x; also convert raw x -> fp16   (main stream)
    ln_stats<<<M_, 256>>>(x, p_xH);

    // 2) spiral-conv scan (LN applied inline from stats) -> g_s
    scan_pass1<<<dim3(NC_, B_ * (D_ / 256)), 256>>>(x, gamma, beta,
                                                    phr, phi, pir, pii);
    scan_pass2<<<B_ * (D_ / 256), 256>>>(hr, hi, phr, phi);
    scan_pass3<<<dim3(NC_, B_ * (D_ / 256)), 256>>>(x, gamma, beta,
                                                    phr, phi, pir, pii,
                                                    cwp_out, s_extra);

    // join: GEMMs need the converted weights
    cudaStreamWaitEvent(0, evJoin, 0);

    // 3) h = s * silu(x @ fc_w^T + fc_b) + x
    gemm_mma<0><<<ngrid, GTHREADS, GSMEM>>>(p_xH, p_fcwH, fc_b, p_s, x, p_h,
                                            1, D_, D_);

    // 4) hn = fp16(LN(h))
    ln_kernel<<<M_, 256>>>(p_h, gamma, beta, p_hnH);

    // 5) t = fp16(silu(hn @ w1^T + b1))
    gemm_mma<1><<<ngrid, GTHREADS, GSMEM>>>(p_hnH, p_w1H, b1, nullptr, nullptr,
                                            p_tH, 1, DF_, D_);

    // 6) out = t @ w2^T + b2 + h
    gemm_mma<2><<<ngrid, GTHREADS, GSMEM>>>(p_tH, p_w2H, b2, p_h, nullptr, out,
                                            out_mul, D_, DF_);
}

// round 16
// speedup vs baseline: 1.0683x; 1.0683x over previous
#include <cuda_runtime.h>
#include <cuda_fp16.h>
#include <math.h>
#include <stdint.h>

// Problem dims (fixed by reference setup_inputs)
#define B_   4
#define L_   2048
#define D_   1024
#define DF_  4096
#define M_   (B_ * L_)        // 8192 rows
#define NC_  32               // scan chunks along L
#define CL_  (L_ / NC_)       // 64
#define BLD  (B_ * L_ * D_)   // 8388608

// ---------------- scratch (device globals; no allocation allowed) ----------
__device__ float  g_s [BLD];
__device__ float  g_h [BLD];
__device__ float2 g_E [B_ * NC_ * D_];
__device__ float2 g_T [B_ * NC_ * D_];
__device__ float2 g_stat[M_];          // per-row (mean, rstd) of x
// fp16 operands (plain fp16 both sides)
__device__ __half g_xH  [M_ * D_];
__device__ __half g_hnH [M_ * D_];
__device__ __half g_tH  [M_ * DF_];
__device__ __half g_fcwH[D_  * D_];
__device__ __half g_w1H [DF_ * D_];
__device__ __half g_w2H [D_  * DF_];

// ======================= helpers ===========================================
__device__ __forceinline__ uint32_t smem_u32(const void* p) {
    return (uint32_t)__cvta_generic_to_shared(p);
}
__device__ __forceinline__ uint32_t packh2(__half a, __half b) {
    __half2 t = __halves2half2(a, b);
    return *reinterpret_cast<uint32_t*>(&t);
}

// ---------------- merged fp16 weight convert --------------------------------
#define W0Q ((D_ * D_) / 4)
#define W1Q ((DF_ * D_) / 4)
#define W2Q ((D_ * DF_) / 4)
__global__ void conv_weights(const float* __restrict__ fcw,
                             const float* __restrict__ w1,
                             const float* __restrict__ w2,
                             __half* __restrict__ ofc,
                             __half* __restrict__ ow1,
                             __half* __restrict__ ow2)
{
    const int total = W0Q + W1Q + W2Q;
    for (int q = blockIdx.x * blockDim.x + threadIdx.x; q < total;
         q += gridDim.x * blockDim.x) {
        const float* in;
        __half* out;
        int i;
        if (q < W0Q)            { in = fcw; out = ofc; i = q; }
        else if (q < W0Q + W1Q) { in = w1;  out = ow1; i = q - W0Q; }
        else                    { in = w2;  out = ow2; i = q - W0Q - W1Q; }
        const float4 v = *reinterpret_cast<const float4*>(in + i * 4);
        *reinterpret_cast<uint2*>(out + i * 4) =
            make_uint2(packh2(__float2half_rn(v.x), __float2half_rn(v.y)),
                       packh2(__float2half_rn(v.z), __float2half_rn(v.w)));
    }
}

// ---------------- LN stats (first LN) + raw-x fp16 convert ------------------
__global__ void ln_stats(const float* __restrict__ x, __half* __restrict__ sp)
{
    const int row = blockIdx.x;
    const int tid = threadIdx.x;
    const float4 v = reinterpret_cast<const float4*>(x + (size_t)row * D_)[tid];

    float s  = v.x + v.y + v.z + v.w;
    float ss = v.x*v.x + v.y*v.y + v.z*v.z + v.w*v.w;
    #pragma unroll
    for (int o = 16; o; o >>= 1) {
        s  += __shfl_xor_sync(0xffffffffu, s,  o);
        ss += __shfl_xor_sync(0xffffffffu, ss, o);
    }
    __shared__ float shs[8], shq[8];
    const int w = tid >> 5, ln = tid & 31;
    if (ln == 0) { shs[w] = s; shq[w] = ss; }
    __syncthreads();
    s = 0.f; ss = 0.f;
    #pragma unroll
    for (int i = 0; i < 8; i++) { s += shs[i]; ss += shq[i]; }

    const float mean = s * (1.0f / D_);
    const float var  = ss * (1.0f / D_) - mean * mean;
    const float rstd = rsqrtf(var + 1e-5f);
    if (tid == 0) g_stat[row] = make_float2(mean, rstd);

    *reinterpret_cast<uint2*>(sp + (size_t)row * D_ + tid*4) =
        make_uint2(packh2(__float2half_rn(v.x), __float2half_rn(v.y)),
                   packh2(__float2half_rn(v.z), __float2half_rn(v.w)));
}

// ---------------- LayerNorm (second LN: full, fp16 out) ---------------------
__global__ void ln_kernel(const float* __restrict__ x,
                          const float* __restrict__ g,
                          const float* __restrict__ bb,
                          __half* __restrict__ sp)
{
    const int row = blockIdx.x;
    const int tid = threadIdx.x;
    const float4 v = reinterpret_cast<const float4*>(x + (size_t)row * D_)[tid];

    float s  = v.x + v.y + v.z + v.w;
    float ss = v.x*v.x + v.y*v.y + v.z*v.z + v.w*v.w;
    #pragma unroll
    for (int o = 16; o; o >>= 1) {
        s  += __shfl_xor_sync(0xffffffffu, s,  o);
        ss += __shfl_xor_sync(0xffffffffu, ss, o);
    }
    __shared__ float shs[8], shq[8];
    const int w = tid >> 5, ln = tid & 31;
    if (ln == 0) { shs[w] = s; shq[w] = ss; }
    __syncthreads();
    s = 0.f; ss = 0.f;
    #pragma unroll
    for (int i = 0; i < 8; i++) { s += shs[i]; ss += shq[i]; }

    const float mean = s * (1.0f / D_);
    const float var  = ss * (1.0f / D_) - mean * mean;
    const float rstd = rsqrtf(var + 1e-5f);

    const float4 gg = reinterpret_cast<const float4*>(g)[tid];
    const float4 bv = reinterpret_cast<const float4*>(bb)[tid];
    const float o0 = (v.x - mean) * rstd * gg.x + bv.x;
    const float o1 = (v.y - mean) * rstd * gg.y + bv.y;
    const float o2 = (v.z - mean) * rstd * gg.z + bv.z;
    const float o3 = (v.w - mean) * rstd * gg.w + bv.w;

    *reinterpret_cast<uint2*>(sp + (size_t)row * D_ + tid*4) =
        make_uint2(packh2(__float2half_rn(o0), __float2half_rn(o1)),
                   packh2(__float2half_rn(o2), __float2half_rn(o3)));
}

// ---------------- spiral-conv scan (3-pass, R12-proven) ----------------------
__device__ __forceinline__ void phazor_a(float pr, float pi, float& ar, float& ai)
{
    const float amag = sqrtf(pr*pr + pi*pi);
    const float e = expf(-amag) / amag;
    ar = pr * e; ai = pi * e;
}

__global__ void scan_pass1(const float* __restrict__ x,
                           const float* __restrict__ lng, const float* __restrict__ lnb,
                           const float* __restrict__ phr, const float* __restrict__ phi,
                           const float* __restrict__ pir, const float* __restrict__ pii)
{
    __shared__ float2 st[CL_];
    const int tid   = threadIdx.x;
    const int chunk = blockIdx.x;
    const int bd    = blockIdx.y;
    const int b     = bd >> 2;
    const int d     = ((bd & 3) << 8) + tid;

    if (tid < CL_) st[tid] = g_stat[b * L_ + chunk * CL_ + tid];
    __syncthreads();

    float ar, ai; phazor_a(phr[d], phi[d], ar, ai);
    const float ir = pir[d], ii = pii[d];
    const float gam = lng[d], bet = lnb[d];

    float cr = 0.f, ci = 0.f;
    const float* xp = x + ((size_t)b * L_ + (size_t)chunk * CL_) * D_ + d;
    #pragma unroll 4
    for (int l = 0; l < CL_; l++) {
        const float2 sr = st[l];
        const float xv = fmaf((xp[(size_t)l * D_] - sr.x) * sr.y, gam, bet);
        const float nr = fmaf(ar, cr, fmaf(-ai, ci, ir * xv));
        const float ni = fmaf(ar, ci, fmaf( ai, cr, ii * xv));
        cr = nr; ci = ni;
    }
    g_E[((size_t)b * NC_ + chunk) * D_ + d] = make_float2(cr, ci);
}

__global__ void scan_pass2(const float* __restrict__ hr, const float* __restrict__ hi,
                           const float* __restrict__ phr, const float* __restrict__ phi)
{
    const int tid = threadIdx.x;
    const int bd  = blockIdx.x;
    const int b   = bd >> 2;
    const int d   = ((bd & 3) << 8) + tid;

    float ar, ai; phazor_a(phr[d], phi[d], ar, ai);
    float qr = ar, qi = ai;        // a^64 via 6 squarings
    #pragma unroll
    for (int i = 0; i < 6; i++) {
        const float nr = qr*qr - qi*qi;
        const float ni = 2.f * qr * qi;
        qr = nr; qi = ni;
    }
    float tr = hr[b * D_ + d], ti = hi[b * D_ + d];

    const float2* Ep = g_E + (size_t)b * NC_ * D_ + d;
    float2*       Tp = g_T + (size_t)b * NC_ * D_ + d;

    #pragma unroll
    for (int g = 0; g < NC_ / 8; g++) {
        float2 ev[8];
        #pragma unroll
        for (int j = 0; j < 8; j++)
            ev[j] = Ep[(size_t)(g * 8 + j) * D_];
        #pragma unroll
        for (int j = 0; j < 8; j++) {
            Tp[(size_t)(g * 8 + j) * D_] = make_float2(tr, ti);
            const float nr = qr*tr - qi*ti + ev[j].x;
            const float ni = qr*ti + qi*tr + ev[j].y;
            tr = nr; ti = ni;
        }
    }
}

__global__ void scan_pass3(const float* __restrict__ x,
                           const float* __restrict__ lng, const float* __restrict__ lnb,
                           const float* __restrict__ phr, const float* __restrict__ phi,
                           const float* __restrict__ pir, const float* __restrict__ pii,
                           float2* __restrict__ cwp_out,
                           float*  __restrict__ s_extra)
{
    __shared__ float2 st[CL_];
    const int tid   = threadIdx.x;
    const int chunk = blockIdx.x;
    const int bd    = blockIdx.y;
    const int b     = bd >> 2;
    const int d     = ((bd & 3) << 8) + tid;

    if (tid < CL_) st[tid] = g_stat[b * L_ + chunk * CL_ + tid];
    __syncthreads();

    float ar, ai; phazor_a(phr[d], phi[d], ar, ai);
    const float ir = pir[d], ii = pii[d];
    const float gam = lng[d], bet = lnb[d];

    const float2 t0 = g_T[((size_t)b * NC_ + chunk) * D_ + d];
    float cr = t0.x, ci = t0.y;

    const size_t base = ((size_t)b * L_ + (size_t)chunk * CL_) * D_ + d;
    #pragma unroll 4
    for (int l = 0; l < CL_; l++) {
        const size_t idx = base + (size_t)l * D_;
        const float2 sr = st[l];
        const float xv = fmaf((x[idx] - sr.x) * sr.y, gam, bet);
        const float nr = fmaf(ar, cr, fmaf(-ai, ci, ir * xv));
        const float ni = fmaf(ar, ci, fmaf( ai, cr, ii * xv));
        cr = nr; ci = ni;
        g_s[idx] = cr;
        if (cwp_out) cwp_out[idx] = make_float2(cr, ci);
        if (s_extra) s_extra[idx] = cr;
    }
}

// =================== fp16 HMMA NT GEMM  (mma.sync m16n8k16) ================
// BM=128 BN=128, 256 threads (8 warps as 2m x 4n, warp tile 64x32),
// 3-stage multistage, 2 CTAs per SM => 16 warps/SM, persistent CTAs.

#define GTHREADS 256
#define ASUBB   8192
#define BSUBB   8192
#define SUBB    (ASUBB + BSUBB)
#define STAGE64 (2 * SUBB)
#define GSTAGES 3
#define GSMEM   (GSTAGES * STAGE64)

__device__ __forceinline__ void cp_async16(uint32_t saddr, const void* gaddr) {
    asm volatile("cp.async.cg.shared.global [%0], [%1], 16;\n"
                 :: "r"(saddr), "l"(gaddr) : "memory");
}
__device__ __forceinline__ void cp_commit() {
    asm volatile("cp.async.commit_group;\n" ::: "memory");
}
__device__ __forceinline__ void cp_wait1() {
    asm volatile("cp.async.wait_group 1;\n" ::: "memory");
}
__device__ __forceinline__ void cp_wait0() {
    asm volatile("cp.async.wait_group 0;\n" ::: "memory");
}
__device__ __forceinline__ void ldmatrix_x4(uint32_t* r, uint32_t addr) {
    asm volatile("ldmatrix.sync.aligned.m8n8.x4.shared.b16 {%0,%1,%2,%3}, [%4];\n"
                 : "=r"(r[0]), "=r"(r[1]), "=r"(r[2]), "=r"(r[3]) : "r"(addr));
}
#define MMA16816(ac, a, b0v, b1v) \
    asm volatile("mma.sync.aligned.m16n8k16.row.col.f32.f16.f16.f32 " \
        "{%0,%1,%2,%3}, {%4,%5,%6,%7}, {%8,%9}, {%0,%1,%2,%3};\n" \
        : "+f"((ac)[0]), "+f"((ac)[1]), "+f"((ac)[2]), "+f"((ac)[3]) \
        : "r"((a)[0]), "r"((a)[1]), "r"((a)[2]), "r"((a)[3]), "r"(b0v), "r"(b1v))

__device__ __forceinline__ void gemm_load_stage64(const __half* __restrict__ Ab,
                                                  const __half* __restrict__ Bb,
                                                  int K, int kt64, char* sm, int tid)
{
    #pragma unroll
    for (int sub = 0; sub < 2; sub++) {
        const int k0 = kt64 * 64 + sub * 32;
        char* s = sm + sub * SUBB;
        #pragma unroll
        for (int h = 0; h < 2; h++) {
            const int ci  = h * GTHREADS + tid;   // 0..511
            const int row = ci >> 2;              // 0..127
            const int c   = ci & 3;
            const int sw  = (c ^ ((row >> 1) & 3)) << 4;
            cp_async16(smem_u32(s + row * 64 + sw), Ab + (size_t)row * K + k0 + c * 8);
        }
        #pragma unroll
        for (int h = 0; h < 2; h++) {
            const int ci  = h * GTHREADS + tid;
            const int row = ci >> 2;
            const int c   = ci & 3;
            const int sw  = (c ^ ((row >> 1) & 3)) << 4;
            cp_async16(smem_u32(s + ASUBB + row * 64 + sw), Bb + (size_t)row * K + k0 + c * 8);
        }
    }
}

template<int EPI>   // 0: h=s*silu(v)+x (f32)  1: silu(v) fp16  2: v+h (f32/cplx)
__global__ void __launch_bounds__(GTHREADS, 2)
gemm_mma(const __half* __restrict__ A, const __half* __restrict__ Bm,
         const float* __restrict__ bias,
         const float* __restrict__ aux1, const float* __restrict__ aux2,
         void* __restrict__ Cout, int out_mul, int N, int K)
{
    extern __shared__ __align__(16) char smem[];

    const int tid  = threadIdx.x;
    const int wid  = tid >> 5, lane = tid & 31;
    const int wm   = wid & 1;          // 2 m-groups of 64
    const int wn   = wid >> 1;         // 4 n-groups of 32
    const int NK   = K / 64;

    const int rA   = wm * 64 + (lane & 15);
    const int rB   = wn * 32 + (lane & 15);
    const int khalf = lane >> 4;
    const int swA  = (rA >> 1) & 3;
    const int swB  = (rB >> 1) & 3;
    const int tr   = lane >> 2;
    const int tc   = (lane & 3) * 2;

    const int nbn = N / 128;
    const int ntiles = (M_ / 128) * nbn;

    for (int t = blockIdx.x; t < ntiles; t += gridDim.x) {
        const int bn = t % nbn, bm = t / nbn;
        const __half* Ab = A  + (size_t)(bm * 128) * K;
        const __half* Bb = Bm + (size_t)(bn * 128) * K;

        float acc[4][4][4];
        #pragma unroll
        for (int i = 0; i < 4; i++)
            #pragma unroll
            for (int j = 0; j < 4; j++)
                #pragma unroll
                for (int q = 0; q < 4; q++) acc[i][j][q] = 0.f;

        gemm_load_stage64(Ab, Bb, K, 0, smem, tid);
        cp_commit();
        gemm_load_stage64(Ab, Bb, K, 1, smem + STAGE64, tid);
        cp_commit();

        for (int kt = 0; kt < NK; kt++) {
            cp_wait1();
            __syncthreads();

            if (kt + 2 < NK)
                gemm_load_stage64(Ab, Bb, K, kt + 2,
                                  smem + ((kt + 2) % GSTAGES) * STAGE64, tid);
            cp_commit();

            char* stg = smem + (kt % GSTAGES) * STAGE64;
            #pragma unroll
            for (int sub = 0; sub < 2; sub++) {
                char* sm = stg + sub * SUBB;
                const uint32_t aBase = smem_u32(sm) + rA * 64;
                const uint32_t bBase = smem_u32(sm + ASUBB) + rB * 64;
                #pragma unroll
                for (int ks = 0; ks < 2; ks++) {
                    uint32_t af[4][4], bfr[2][4];
                    const int chA = ((ks * 2 + khalf) ^ swA) << 4;
                    const int chB = ((ks * 2 + khalf) ^ swB) << 4;
                    #pragma unroll
                    for (int mi = 0; mi < 4; mi++)
                        ldmatrix_x4(af[mi], aBase + mi * 1024 + chA);
                    #pragma unroll
                    for (int bj = 0; bj < 2; bj++)
                        ldmatrix_x4(bfr[bj], bBase + bj * 1024 + chB);
                    #pragma unroll
                    for (int mi = 0; mi < 4; mi++)
                        #pragma unroll
                        for (int nj = 0; nj < 4; nj++)
                            MMA16816(acc[mi][nj], af[mi],
                                     bfr[nj >> 1][nj & 1], bfr[nj >> 1][(nj & 1) + 2]);
                }
            }
        }
        cp_wait0();
        __syncthreads();

        // ---- epilogue ----
        #pragma unroll
        for (int mi = 0; mi < 4; mi++) {
            #pragma unroll
            for (int r2 = 0; r2 < 2; r2++) {
                const size_t grow = (size_t)bm * 128 + wm * 64 + mi * 16 + tr + r2 * 8;
                #pragma unroll
                for (int nj = 0; nj < 4; nj++) {
                    const int gcol = bn * 128 + wn * 32 + nj * 8 + tc;
                    float v0 = acc[mi][nj][r2 * 2]     + bias[gcol];
                    float v1 = acc[mi][nj][r2 * 2 + 1] + bias[gcol + 1];
                    const size_t idx = grow * (size_t)N + gcol;
                    if (EPI == 0) {
                        const float2 a1 = *reinterpret_cast<const float2*>(aux1 + idx);
                        const float2 a2 = *reinterpret_cast<const float2*>(aux2 + idx);
                        v0 = a1.x * (v0 / (1.f + __expf(-v0))) + a2.x;
                        v1 = a1.y * (v1 / (1.f + __expf(-v1))) + a2.y;
                        *reinterpret_cast<float2*>((float*)Cout + idx) = make_float2(v0, v1);
                    } else if (EPI == 1) {
                        v0 = v0 / (1.f + __expf(-v0));
                        v1 = v1 / (1.f + __expf(-v1));
                        __half* T = (__half*)Cout;
                        *reinterpret_cast<uint32_t*>(T + idx) =
                            packh2(__float2half_rn(v0), __float2half_rn(v1));
                    } else {
                        const float2 a1 = *reinterpret_cast<const float2*>(aux1 + idx);
                        v0 += a1.x; v1 += a1.y;
                        if (out_mul == 2) {
                            float* C = (float*)Cout;
                            C[idx * 2]     = v0; C[idx * 2 + 1] = 0.f;
                            C[idx * 2 + 2] = v1; C[idx * 2 + 3] = 0.f;
                        } else {
                            *reinterpret_cast<float2*>((float*)Cout + idx) = make_float2(v0, v1);
                        }
                    }
                }
            }
        }
        __syncthreads();
    }
}

// ---------------- launch ---------------------------------------------------
extern "C" void kernel_launch(void* const* d_in, const int* in_sizes, int n_in,
                              void* d_out, int out_size)
{
    const float* x     = (const float*)d_in[0];
    const float* hr    = (const float*)d_in[1];
    const float* hi    = (const float*)d_in[2];
    const float* phr   = (const float*)d_in[3];
    const float* phi   = (const float*)d_in[4];
    const float* pir   = (const float*)d_in[5];
    const float* pii   = (const float*)d_in[6];
    const float* gamma = (const float*)d_in[7];
    const float* beta  = (const float*)d_in[8];
    const float* fc_w  = (const float*)d_in[9];
    const float* fc_b  = (const float*)d_in[10];
    const float* w1    = (const float*)d_in[11];
    const float* b1    = (const float*)d_in[12];
    const float* w2    = (const float*)d_in[13];
    const float* b2    = (const float*)d_in[14];
    float* out = (float*)d_out;

    float *p_s, *p_h;
    __half *p_xH, *p_hnH, *p_tH, *p_fcwH, *p_w1H, *p_w2H;
    cudaGetSymbolAddress((void**)&p_s,    g_s);
    cudaGetSymbolAddress((void**)&p_h,    g_h);
    cudaGetSymbolAddress((void**)&p_xH,   g_xH);
    cudaGetSymbolAddress((void**)&p_hnH,  g_hnH);
    cudaGetSymbolAddress((void**)&p_tH,   g_tH);
    cudaGetSymbolAddress((void**)&p_fcwH, g_fcwH);
    cudaGetSymbolAddress((void**)&p_w1H,  g_w1H);
    cudaGetSymbolAddress((void**)&p_w2H,  g_w2H);

    cudaFuncSetAttribute(gemm_mma<0>, cudaFuncAttributeMaxDynamicSharedMemorySize, GSMEM);
    cudaFuncSetAttribute(gemm_mma<1>, cudaFuncAttributeMaxDynamicSharedMemorySize, GSMEM);
    cudaFuncSetAttribute(gemm_mma<2>, cudaFuncAttributeMaxDynamicSharedMemorySize, GSMEM);

    int nsm = 148;
    cudaDeviceGetAttribute(&nsm, cudaDevAttrMultiProcessorCount, 0);
    const int ngrid = 2 * nsm;

    // Adapt to output packing (second output new_hidden is complex64 [B,L,D])
    float2* cwp_out = nullptr;
    float*  s_extra = nullptr;
    int out_mul = 1;
    if (out_size == 3 * BLD) {
        cwp_out = (float2*)(out + (size_t)BLD);
    } else if (out_size == 4 * BLD) {
        out_mul = 2;
        cwp_out = (float2*)(out + 2 * (size_t)BLD);
    } else if (out_size == 2 * BLD) {
        s_extra = out + (size_t)BLD;
    }

    // 0) merged fp16 weight conversion
    conv_weights<<<1024, 256>>>(fc_w, w1, w2, p_fcwH, p_w1H, p_w2H);

    // 1) per-row LN stats of x; also convert raw x -> fp16
    ln_stats<<<M_, 256>>>(x, p_xH);

    // 2) spiral-conv scan (LN applied inline from stats) -> g_s
    scan_pass1<<<dim3(NC_, B_ * (D_ / 256)), 256>>>(x, gamma, beta,
                                                    phr, phi, pir, pii);
    scan_pass2<<<B_ * (D_ / 256), 256>>>(hr, hi, phr, phi);
    scan_pass3<<<dim3(NC_, B_ * (D_ / 256)), 256>>>(x, gamma, beta,
                                                    phr, phi, pir, pii,
                                                    cwp_out, s_extra);

    // 3) h = s * silu(x @ fc_w^T + fc_b) + x
    gemm_mma<0><<<ngrid, GTHREADS, GSMEM>>>(p_xH, p_fcwH, fc_b, p_s, x, p_h,
                                            1, D_, D_);

    // 4) hn = fp16(LN(h))
    ln_kernel<<<M_, 256>>>(p_h, gamma, beta, p_hnH);

    // 5) t = fp16(silu(hn @ w1^T + b1))
    gemm_mma<1><<<ngrid, GTHREADS, GSMEM>>>(p_hnH, p_w1H, b1, nullptr, nullptr,
                                            p_tH, 1, DF_, D_);

    // 6) out = t @ w2^T + b2 + h
    gemm_mma<2><<<ngrid, GTHREADS, GSMEM>>>(p_tH, p_w2H, b2, p_h, nullptr, out,
                                            out_mul, D_, DF_);
}

// round 17
// speedup vs baseline: 1.0878x; 1.0183x over previous
#include <cuda_runtime.h>
#include <cuda_fp16.h>
#include <math.h>
#include <stdint.h>

// Problem dims (fixed by reference setup_inputs)
#define B_   4
#define L_   2048
#define D_   1024
#define DF_  4096
#define M_   (B_ * L_)        // 8192 rows
#define NC_  32               // scan chunks along L
#define CL_  (L_ / NC_)       // 64
#define BLD  (B_ * L_ * D_)   // 8388608

// ---------------- scratch (device globals; no allocation allowed) ----------
__device__ float  g_s [BLD];
__device__ float  g_h [BLD];
__device__ float2 g_E [B_ * NC_ * D_];
__device__ float2 g_T [B_ * NC_ * D_];
__device__ float2 g_stat[M_];          // per-row (mean, rstd) of x
// fp16 operands (plain fp16 both sides)
__device__ __half g_xH  [M_ * D_];
__device__ __half g_hnH [M_ * D_];
__device__ __half g_tH  [M_ * DF_];
__device__ __half g_fcwH[D_  * D_];
__device__ __half g_w1H [DF_ * D_];
__device__ __half g_w2H [D_  * DF_];

// ======================= helpers ===========================================
__device__ __forceinline__ uint32_t smem_u32(const void* p) {
    return (uint32_t)__cvta_generic_to_shared(p);
}
__device__ __forceinline__ uint32_t packh2(__half a, __half b) {
    __half2 t = __halves2half2(a, b);
    return *reinterpret_cast<uint32_t*>(&t);
}

// ---------------- merged fp16 weight convert --------------------------------
#define W0Q ((D_ * D_) / 4)
#define W1Q ((DF_ * D_) / 4)
#define W2Q ((D_ * DF_) / 4)
__global__ void conv_weights(const float* __restrict__ fcw,
                             const float* __restrict__ w1,
                             const float* __restrict__ w2,
                             __half* __restrict__ ofc,
                             __half* __restrict__ ow1,
                             __half* __restrict__ ow2)
{
    const int total = W0Q + W1Q + W2Q;
    for (int q = blockIdx.x * blockDim.x + threadIdx.x; q < total;
         q += gridDim.x * blockDim.x) {
        const float* in;
        __half* out;
        int i;
        if (q < W0Q)            { in = fcw; out = ofc; i = q; }
        else if (q < W0Q + W1Q) { in = w1;  out = ow1; i = q - W0Q; }
        else                    { in = w2;  out = ow2; i = q - W0Q - W1Q; }
        const float4 v = *reinterpret_cast<const float4*>(in + i * 4);
        *reinterpret_cast<uint2*>(out + i * 4) =
            make_uint2(packh2(__float2half_rn(v.x), __float2half_rn(v.y)),
                       packh2(__float2half_rn(v.z), __float2half_rn(v.w)));
    }
}

// ---------------- LN stats (first LN) + raw-x fp16 convert ------------------
__global__ void ln_stats(const float* __restrict__ x, __half* __restrict__ sp)
{
    const int row = blockIdx.x;
    const int tid = threadIdx.x;
    const float4 v = reinterpret_cast<const float4*>(x + (size_t)row * D_)[tid];

    float s  = v.x + v.y + v.z + v.w;
    float ss = v.x*v.x + v.y*v.y + v.z*v.z + v.w*v.w;
    #pragma unroll
    for (int o = 16; o; o >>= 1) {
        s  += __shfl_xor_sync(0xffffffffu, s,  o);
        ss += __shfl_xor_sync(0xffffffffu, ss, o);
    }
    __shared__ float shs[8], shq[8];
    const int w = tid >> 5, ln = tid & 31;
    if (ln == 0) { shs[w] = s; shq[w] = ss; }
    __syncthreads();
    s = 0.f; ss = 0.f;
    #pragma unroll
    for (int i = 0; i < 8; i++) { s += shs[i]; ss += shq[i]; }

    const float mean = s * (1.0f / D_);
    const float var  = ss * (1.0f / D_) - mean * mean;
    const float rstd = rsqrtf(var + 1e-5f);
    if (tid == 0) g_stat[row] = make_float2(mean, rstd);

    *reinterpret_cast<uint2*>(sp + (size_t)row * D_ + tid*4) =
        make_uint2(packh2(__float2half_rn(v.x), __float2half_rn(v.y)),
                   packh2(__float2half_rn(v.z), __float2half_rn(v.w)));
}

// ---------------- LayerNorm (second LN: full, fp16 out) ---------------------
__global__ void ln_kernel(const float* __restrict__ x,
                          const float* __restrict__ g,
                          const float* __restrict__ bb,
                          __half* __restrict__ sp)
{
    const int row = blockIdx.x;
    const int tid = threadIdx.x;
    const float4 v = reinterpret_cast<const float4*>(x + (size_t)row * D_)[tid];

    float s  = v.x + v.y + v.z + v.w;
    float ss = v.x*v.x + v.y*v.y + v.z*v.z + v.w*v.w;
    #pragma unroll
    for (int o = 16; o; o >>= 1) {
        s  += __shfl_xor_sync(0xffffffffu, s,  o);
        ss += __shfl_xor_sync(0xffffffffu, ss, o);
    }
    __shared__ float shs[8], shq[8];
    const int w = tid >> 5, ln = tid & 31;
    if (ln == 0) { shs[w] = s; shq[w] = ss; }
    __syncthreads();
    s = 0.f; ss = 0.f;
    #pragma unroll
    for (int i = 0; i < 8; i++) { s += shs[i]; ss += shq[i]; }

    const float mean = s * (1.0f / D_);
    const float var  = ss * (1.0f / D_) - mean * mean;
    const float rstd = rsqrtf(var + 1e-5f);

    const float4 gg = reinterpret_cast<const float4*>(g)[tid];
    const float4 bv = reinterpret_cast<const float4*>(bb)[tid];
    const float o0 = (v.x - mean) * rstd * gg.x + bv.x;
    const float o1 = (v.y - mean) * rstd * gg.y + bv.y;
    const float o2 = (v.z - mean) * rstd * gg.z + bv.z;
    const float o3 = (v.w - mean) * rstd * gg.w + bv.w;

    *reinterpret_cast<uint2*>(sp + (size_t)row * D_ + tid*4) =
        make_uint2(packh2(__float2half_rn(o0), __float2half_rn(o1)),
                   packh2(__float2half_rn(o2), __float2half_rn(o3)));
}

// ---------------- spiral-conv scan (3-pass, R12-proven) ----------------------
__device__ __forceinline__ void phazor_a(float pr, float pi, float& ar, float& ai)
{
    const float amag = sqrtf(pr*pr + pi*pi);
    const float e = expf(-amag) / amag;
    ar = pr * e; ai = pi * e;
}

__global__ void scan_pass1(const float* __restrict__ x,
                           const float* __restrict__ lng, const float* __restrict__ lnb,
                           const float* __restrict__ phr, const float* __restrict__ phi,
                           const float* __restrict__ pir, const float* __restrict__ pii)
{
    __shared__ float2 st[CL_];
    const int tid   = threadIdx.x;
    const int chunk = blockIdx.x;
    const int bd    = blockIdx.y;
    const int b     = bd >> 2;
    const int d     = ((bd & 3) << 8) + tid;

    if (tid < CL_) st[tid] = g_stat[b * L_ + chunk * CL_ + tid];
    __syncthreads();

    float ar, ai; phazor_a(phr[d], phi[d], ar, ai);
    const float ir = pir[d], ii = pii[d];
    const float gam = lng[d], bet = lnb[d];

    float cr = 0.f, ci = 0.f;
    const float* xp = x + ((size_t)b * L_ + (size_t)chunk * CL_) * D_ + d;
    #pragma unroll 4
    for (int l = 0; l < CL_; l++) {
        const float2 sr = st[l];
        const float xv = fmaf((xp[(size_t)l * D_] - sr.x) * sr.y, gam, bet);
        const float nr = fmaf(ar, cr, fmaf(-ai, ci, ir * xv));
        const float ni = fmaf(ar, ci, fmaf( ai, cr, ii * xv));
        cr = nr; ci = ni;
    }
    g_E[((size_t)b * NC_ + chunk) * D_ + d] = make_float2(cr, ci);
}

__global__ void scan_pass2(const float* __restrict__ hr, const float* __restrict__ hi,
                           const float* __restrict__ phr, const float* __restrict__ phi)
{
    const int tid = threadIdx.x;
    const int bd  = blockIdx.x;
    const int b   = bd >> 2;
    const int d   = ((bd & 3) << 8) + tid;

    float ar, ai; phazor_a(phr[d], phi[d], ar, ai);
    float qr = ar, qi = ai;        // a^64 via 6 squarings
    #pragma unroll
    for (int i = 0; i < 6; i++) {
        const float nr = qr*qr - qi*qi;
        const float ni = 2.f * qr * qi;
        qr = nr; qi = ni;
    }
    float tr = hr[b * D_ + d], ti = hi[b * D_ + d];

    const float2* Ep = g_E + (size_t)b * NC_ * D_ + d;
    float2*       Tp = g_T + (size_t)b * NC_ * D_ + d;

    #pragma unroll
    for (int g = 0; g < NC_ / 8; g++) {
        float2 ev[8];
        #pragma unroll
        for (int j = 0; j < 8; j++)
            ev[j] = Ep[(size_t)(g * 8 + j) * D_];
        #pragma unroll
        for (int j = 0; j < 8; j++) {
            Tp[(size_t)(g * 8 + j) * D_] = make_float2(tr, ti);
            const float nr = qr*tr - qi*ti + ev[j].x;
            const float ni = qr*ti + qi*tr + ev[j].y;
            tr = nr; ti = ni;
        }
    }
}

__global__ void scan_pass3(const float* __restrict__ x,
                           const float* __restrict__ lng, const float* __restrict__ lnb,
                           const float* __restrict__ phr, const float* __restrict__ phi,
                           const float* __restrict__ pir, const float* __restrict__ pii,
                           float2* __restrict__ cwp_out,
                           float*  __restrict__ s_extra)
{
    __shared__ float2 st[CL_];
    const int tid   = threadIdx.x;
    const int chunk = blockIdx.x;
    const int bd    = blockIdx.y;
    const int b     = bd >> 2;
    const int d     = ((bd & 3) << 8) + tid;

    if (tid < CL_) st[tid] = g_stat[b * L_ + chunk * CL_ + tid];
    __syncthreads();

    float ar, ai; phazor_a(phr[d], phi[d], ar, ai);
    const float ir = pir[d], ii = pii[d];
    const float gam = lng[d], bet = lnb[d];

    const float2 t0 = g_T[((size_t)b * NC_ + chunk) * D_ + d];
    float cr = t0.x, ci = t0.y;

    const size_t base = ((size_t)b * L_ + (size_t)chunk * CL_) * D_ + d;
    #pragma unroll 4
    for (int l = 0; l < CL_; l++) {
        const size_t idx = base + (size_t)l * D_;
        const float2 sr = st[l];
        const float xv = fmaf((x[idx] - sr.x) * sr.y, gam, bet);
        const float nr = fmaf(ar, cr, fmaf(-ai, ci, ir * xv));
        const float ni = fmaf(ar, ci, fmaf( ai, cr, ii * xv));
        cr = nr; ci = ni;
        g_s[idx] = cr;
        if (cwp_out) cwp_out[idx] = make_float2(cr, ci);
        if (s_extra) s_extra[idx] = cr;
    }
}

// =================== fp16 HMMA NT GEMM  (mma.sync m16n8k16) ================
// BM=128 BN=128, 512 threads (16 warps as 4m x 4n, warp tile 32x32),
// 3-stage multistage, 2 CTAs per SM => 32 warps/SM, persistent CTAs.

#define GTHREADS 512
#define ASUBB   8192
#define BSUBB   8192
#define SUBB    (ASUBB + BSUBB)
#define STAGE64 (2 * SUBB)
#define GSTAGES 3
#define GSMEM   (GSTAGES * STAGE64)

__device__ __forceinline__ void cp_async16(uint32_t saddr, const void* gaddr) {
    asm volatile("cp.async.cg.shared.global [%0], [%1], 16;\n"
                 :: "r"(saddr), "l"(gaddr) : "memory");
}
__device__ __forceinline__ void cp_commit() {
    asm volatile("cp.async.commit_group;\n" ::: "memory");
}
__device__ __forceinline__ void cp_wait1() {
    asm volatile("cp.async.wait_group 1;\n" ::: "memory");
}
__device__ __forceinline__ void cp_wait0() {
    asm volatile("cp.async.wait_group 0;\n" ::: "memory");
}
__device__ __forceinline__ void ldmatrix_x4(uint32_t* r, uint32_t addr) {
    asm volatile("ldmatrix.sync.aligned.m8n8.x4.shared.b16 {%0,%1,%2,%3}, [%4];\n"
                 : "=r"(r[0]), "=r"(r[1]), "=r"(r[2]), "=r"(r[3]) : "r"(addr));
}
#define MMA16816(ac, a, b0v, b1v) \
    asm volatile("mma.sync.aligned.m16n8k16.row.col.f32.f16.f16.f32 " \
        "{%0,%1,%2,%3}, {%4,%5,%6,%7}, {%8,%9}, {%0,%1,%2,%3};\n" \
        : "+f"((ac)[0]), "+f"((ac)[1]), "+f"((ac)[2]), "+f"((ac)[3]) \
        : "r"((a)[0]), "r"((a)[1]), "r"((a)[2]), "r"((a)[3]), "r"(b0v), "r"(b1v))

__device__ __forceinline__ void gemm_load_stage64(const __half* __restrict__ Ab,
                                                  const __half* __restrict__ Bb,
                                                  int K, int kt64, char* sm, int tid)
{
    #pragma unroll
    for (int sub = 0; sub < 2; sub++) {
        const int k0 = kt64 * 64 + sub * 32;
        char* s = sm + sub * SUBB;
        {   // A subtile: 512 chunks of 16B, one per thread
            const int row = tid >> 2;
            const int c   = tid & 3;
            const int sw  = (c ^ ((row >> 1) & 3)) << 4;
            cp_async16(smem_u32(s + row * 64 + sw), Ab + (size_t)row * K + k0 + c * 8);
        }
        {   // B subtile
            const int row = tid >> 2;
            const int c   = tid & 3;
            const int sw  = (c ^ ((row >> 1) & 3)) << 4;
            cp_async16(smem_u32(s + ASUBB + row * 64 + sw), Bb + (size_t)row * K + k0 + c * 8);
        }
    }
}

template<int EPI>   // 0: h=s*silu(v)+x (f32)  1: silu(v) fp16  2: v+h (f32/cplx)
__global__ void __launch_bounds__(GTHREADS, 2)
gemm_mma(const __half* __restrict__ A, const __half* __restrict__ Bm,
         const float* __restrict__ bias,
         const float* __restrict__ aux1, const float* __restrict__ aux2,
         void* __restrict__ Cout, int out_mul, int N, int K)
{
    extern __shared__ __align__(16) char smem[];

    const int tid  = threadIdx.x;
    const int wid  = tid >> 5, lane = tid & 31;
    const int wm   = wid & 3;          // 4 m-groups of 32
    const int wn   = wid >> 2;         // 4 n-groups of 32
    const int NK   = K / 64;

    const int rA   = wm * 32 + (lane & 15);
    const int rB   = wn * 32 + (lane & 15);
    const int khalf = lane >> 4;
    const int swA  = (rA >> 1) & 3;
    const int swB  = (rB >> 1) & 3;
    const int tr   = lane >> 2;
    const int tc   = (lane & 3) * 2;

    const int nbn = N / 128;
    const int ntiles = (M_ / 128) * nbn;

    for (int t = blockIdx.x; t < ntiles; t += gridDim.x) {
        const int bn = t % nbn, bm = t / nbn;
        const __half* Ab = A  + (size_t)(bm * 128) * K;
        const __half* Bb = Bm + (size_t)(bn * 128) * K;

        float acc[2][4][4];
        #pragma unroll
        for (int i = 0; i < 2; i++)
            #pragma unroll
            for (int j = 0; j < 4; j++)
                #pragma unroll
                for (int q = 0; q < 4; q++) acc[i][j][q] = 0.f;

        gemm_load_stage64(Ab, Bb, K, 0, smem, tid);
        cp_commit();
        gemm_load_stage64(Ab, Bb, K, 1, smem + STAGE64, tid);
        cp_commit();

        for (int kt = 0; kt < NK; kt++) {
            cp_wait1();
            __syncthreads();

            if (kt + 2 < NK)
                gemm_load_stage64(Ab, Bb, K, kt + 2,
                                  smem + ((kt + 2) % GSTAGES) * STAGE64, tid);
            cp_commit();

            char* stg = smem + (kt % GSTAGES) * STAGE64;
            #pragma unroll
            for (int sub = 0; sub < 2; sub++) {
                char* sm = stg + sub * SUBB;
                const uint32_t aBase = smem_u32(sm) + rA * 64;
                const uint32_t bBase = smem_u32(sm + ASUBB) + rB * 64;
                #pragma unroll
                for (int ks = 0; ks < 2; ks++) {
                    uint32_t af[2][4], bfr[2][4];
                    const int chA = ((ks * 2 + khalf) ^ swA) << 4;
                    const int chB = ((ks * 2 + khalf) ^ swB) << 4;
                    #pragma unroll
                    for (int mi = 0; mi < 2; mi++)
                        ldmatrix_x4(af[mi], aBase + mi * 1024 + chA);
                    #pragma unroll
                    for (int bj = 0; bj < 2; bj++)
                        ldmatrix_x4(bfr[bj], bBase + bj * 1024 + chB);
                    #pragma unroll
                    for (int mi = 0; mi < 2; mi++)
                        #pragma unroll
                        for (int nj = 0; nj < 4; nj++)
                            MMA16816(acc[mi][nj], af[mi],
                                     bfr[nj >> 1][nj & 1], bfr[nj >> 1][(nj & 1) + 2]);
                }
            }
        }
        cp_wait0();
        __syncthreads();

        // ---- epilogue ----
        #pragma unroll
        for (int mi = 0; mi < 2; mi++) {
            #pragma unroll
            for (int r2 = 0; r2 < 2; r2++) {
                const size_t grow = (size_t)bm * 128 + wm * 32 + mi * 16 + tr + r2 * 8;
                #pragma unroll
                for (int nj = 0; nj < 4; nj++) {
                    const int gcol = bn * 128 + wn * 32 + nj * 8 + tc;
                    float v0 = acc[mi][nj][r2 * 2]     + bias[gcol];
                    float v1 = acc[mi][nj][r2 * 2 + 1] + bias[gcol + 1];
                    const size_t idx = grow * (size_t)N + gcol;
                    if (EPI == 0) {
                        const float2 a1 = *reinterpret_cast<const float2*>(aux1 + idx);
                        const float2 a2 = *reinterpret_cast<const float2*>(aux2 + idx);
                        v0 = a1.x * (v0 / (1.f + __expf(-v0))) + a2.x;
                        v1 = a1.y * (v1 / (1.f + __expf(-v1))) + a2.y;
                        *reinterpret_cast<float2*>((float*)Cout + idx) = make_float2(v0, v1);
                    } else if (EPI == 1) {
                        v0 = v0 / (1.f + __expf(-v0));
                        v1 = v1 / (1.f + __expf(-v1));
                        __half* T = (__half*)Cout;
                        *reinterpret_cast<uint32_t*>(T + idx) =
                            packh2(__float2half_rn(v0), __float2half_rn(v1));
                    } else {
                        const float2 a1 = *reinterpret_cast<const float2*>(aux1 + idx);
                        v0 += a1.x; v1 += a1.y;
                        if (out_mul == 2) {
                            float* C = (float*)Cout;
                            C[idx * 2]     = v0; C[idx * 2 + 1] = 0.f;
                            C[idx * 2 + 2] = v1; C[idx * 2 + 3] = 0.f;
                        } else {
                            *reinterpret_cast<float2*>((float*)Cout + idx) = make_float2(v0, v1);
                        }
                    }
                }
            }
        }
        __syncthreads();
    }
}

// ---------------- launch ---------------------------------------------------
extern "C" void kernel_launch(void* const* d_in, const int* in_sizes, int n_in,
                              void* d_out, int out_size)
{
    const float* x     = (const float*)d_in[0];
    const float* hr    = (const float*)d_in[1];
    const float* hi    = (const float*)d_in[2];
    const float* phr   = (const float*)d_in[3];
    const float* phi   = (const float*)d_in[4];
    const float* pir   = (const float*)d_in[5];
    const float* pii   = (const float*)d_in[6];
    const float* gamma = (const float*)d_in[7];
    const float* beta  = (const float*)d_in[8];
    const float* fc_w  = (const float*)d_in[9];
    const float* fc_b  = (const float*)d_in[10];
    const float* w1    = (const float*)d_in[11];
    const float* b1    = (const float*)d_in[12];
    const float* w2    = (const float*)d_in[13];
    const float* b2    = (const float*)d_in[14];
    float* out = (float*)d_out;

    float *p_s, *p_h;
    __half *p_xH, *p_hnH, *p_tH, *p_fcwH, *p_w1H, *p_w2H;
    cudaGetSymbolAddress((void**)&p_s,    g_s);
    cudaGetSymbolAddress((void**)&p_h,    g_h);
    cudaGetSymbolAddress((void**)&p_xH,   g_xH);
    cudaGetSymbolAddress((void**)&p_hnH,  g_hnH);
    cudaGetSymbolAddress((void**)&p_tH,   g_tH);
    cudaGetSymbolAddress((void**)&p_fcwH, g_fcwH);
    cudaGetSymbolAddress((void**)&p_w1H,  g_w1H);
    cudaGetSymbolAddress((void**)&p_w2H,  g_w2H);

    cudaFuncSetAttribute(gemm_mma<0>, cudaFuncAttributeMaxDynamicSharedMemorySize, GSMEM);
    cudaFuncSetAttribute(gemm_mma<1>, cudaFuncAttributeMaxDynamicSharedMemorySize, GSMEM);
    cudaFuncSetAttribute(gemm_mma<2>, cudaFuncAttributeMaxDynamicSharedMemorySize, GSMEM);

    int nsm = 148;
    cudaDeviceGetAttribute(&nsm, cudaDevAttrMultiProcessorCount, 0);
    const int ngrid = 2 * nsm;

    // Adapt to output packing (second output new_hidden is complex64 [B,L,D])
    float2* cwp_out = nullptr;
    float*  s_extra = nullptr;
    int out_mul = 1;
    if (out_size == 3 * BLD) {
        cwp_out = (float2*)(out + (size_t)BLD);
    } else if (out_size == 4 * BLD) {
        out_mul = 2;
        cwp_out = (float2*)(out + 2 * (size_t)BLD);
    } else if (out_size == 2 * BLD) {
        s_extra = out + (size_t)BLD;
    }

    // 0) merged fp16 weight conversion
    conv_weights<<<1024, 256>>>(fc_w, w1, w2, p_fcwH, p_w1H, p_w2H);

    // 1) per-row LN stats of x; also convert raw x -> fp16
    ln_stats<<<M_, 256>>>(x, p_xH);

    // 2) spiral-conv scan (LN applied inline from stats) -> g_s
    scan_pass1<<<dim3(NC_, B_ * (D_ / 256)), 256>>>(x, gamma, beta,
                                                    phr, phi, pir, pii);
    scan_pass2<<<B_ * (D_ / 256), 256>>>(hr, hi, phr, phi);
    scan_pass3<<<dim3(NC_, B_ * (D_ / 256)), 256>>>(x, gamma, beta,
                                                    phr, phi, pir, pii,
                                                    cwp_out, s_extra);

    // 3) h = s * silu(x @ fc_w^T + fc_b) + x
    gemm_mma<0><<<ngrid, GTHREADS, GSMEM>>>(p_xH, p_fcwH, fc_b, p_s, x, p_h,
                                            1, D_, D_);

    // 4) hn = fp16(LN(h))
    ln_kernel<<<M_, 256>>>(p_h, gamma, beta, p_hnH);

    // 5) t = fp16(silu(hn @ w1^T + b1))
    gemm_mma<1><<<ngrid, GTHREADS, GSMEM>>>(p_hnH, p_w1H, b1, nullptr, nullptr,
                                            p_tH, 1, DF_, D_);

    // 6) out = t @ w2^T + b2 + h
    gemm_mma<2><<<ngrid, GTHREADS, GSMEM>>>(p_tH, p_w2H, b2, p_h, nullptr, out,
                                            out_mul, D_, DF_);
}